// round 6
// baseline (speedup 1.0000x reference)
#include <cuda_runtime.h>
#include <cuda_fp16.h>
#include <cstdint>

// ---------------------------------------------------------------------------
// out (32,4096,512) f32, hidden (2,32,512), W (512,512), b(512), v(512)
// Output = [context (32*512) | attn (32*4096)] f32.
//
// R6: 2 CTAs/SM. ROWS=64, 256 thr (8 warps, 2Mx4N, warp tile M32xN32),
// SMEM 112KB/CTA: A 64KB resident + W 3-slot 16KB ring (distance-1 prefetch).
// bias/v read from L2 in the per-chunk epilogue. Per-slice barrier drains are
// covered by the co-resident CTA.
// ---------------------------------------------------------------------------
#define B_DIM   32
#define S_DIM   4096
#define H_DIM   512
#define ROWS    64
#define NTILES  2048
#define NSLICE  32
#define SLICE_B 16384
#define RINGN   3
#define NT      256

// SMEM layout (bytes)
#define SM_A     0                  // 64 rows x 1024B fp16 (swizzled)
#define SM_RING  65536              // 3 x 16384
#define SM_SC2   65536              // scratch (reuses ring after mainloop)
#define SM_SW2   66560              // 64 f32 softmax weights
#define SM_RED   66816              // 8 f32
#define SM_TOTAL 114688

#define SWZ(byte_in_row, row) ((byte_in_row) ^ (((row) & 7) << 4))

// -------------------- device-global scratch --------------------------------
__device__ __align__(16) unsigned char g_W16[H_DIM * H_DIM * 2];
__device__ float g_bias[B_DIM * H_DIM];
__device__ float g_scores[B_DIM * S_DIM];
__device__ float g_pm[NTILES];
__device__ float g_pl[NTILES];
__device__ float g_pc[NTILES * H_DIM];

// -------------------- helpers ----------------------------------------------
__device__ __forceinline__ uint32_t smem_u32(const void* p) {
    uint32_t a;
    asm("{ .reg .u64 t; cvta.to.shared.u64 t, %1; cvt.u32.u64 %0, t; }"
        : "=r"(a) : "l"(p));
    return a;
}
__device__ __forceinline__ void cp_async16(uint32_t dst, const void* src) {
    asm volatile("cp.async.cg.shared.global [%0], [%1], 16;"
                 :: "r"(dst), "l"(__cvta_generic_to_global(src)) : "memory");
}
#define CP_COMMIT() asm volatile("cp.async.commit_group;" ::: "memory")
#define CP_WAIT1()  asm volatile("cp.async.wait_group 1;" ::: "memory")

#define LDSM_X4(r0, r1, r2, r3, addr)                                          \
    asm volatile("ldmatrix.sync.aligned.m8n8.x4.shared.b16 {%0,%1,%2,%3}, [%4];" \
                 : "=r"(r0), "=r"(r1), "=r"(r2), "=r"(r3) : "r"(addr))

#define MMA16816(c0, c1, c2, c3, a0, a1, a2, a3, b0, b1)                       \
    asm volatile("mma.sync.aligned.m16n8k16.row.col.f32.f16.f16.f32 "          \
                 "{%0,%1,%2,%3}, {%4,%5,%6,%7}, {%8,%9}, {%0,%1,%2,%3};"       \
                 : "+f"(c0), "+f"(c1), "+f"(c2), "+f"(c3)                      \
                 : "r"(a0), "r"(a1), "r"(a2), "r"(a3), "r"(b0), "r"(b1))

__device__ __forceinline__ float tanh_fast(float x) {
    float e = __expf(2.0f * x);
    return 1.0f - __fdividef(2.0f, e + 1.0f);
}

// ---------------------------------------------------------------------------
// Kernel 0: prep — W f32 -> fp16 slice-major (slice: 128 N-rows x 64 K-cols,
// 128B rows, SW128 swizzle); bias = b + hidden[-1].
// ---------------------------------------------------------------------------
__global__ void prep_kernel(const float* __restrict__ W,
                            const float* __restrict__ bvec,
                            const float* __restrict__ hidden,
                            int hid_off) {
    int idx = blockIdx.x * blockDim.x + threadIdx.x;
    int stride = gridDim.x * blockDim.x;
    for (int i = idx; i < H_DIM * H_DIM; i += stride) {
        int n = i >> 9, k = i & 511;
        int g = (n >> 7) * 8 + (k >> 6);
        uint32_t off = (uint32_t)g * SLICE_B + (uint32_t)(n & 127) * 128u
                     + ((uint32_t)((k & 63) * 2) ^ (((uint32_t)n & 7) << 4));
        *(__half*)(g_W16 + off) = __float2half_rn(W[i]);
    }
    for (int i = idx; i < B_DIM * H_DIM; i += stride)
        g_bias[i] = bvec[i & 511] + hidden[hid_off + i];
}

__global__ void pad_kernel() {}

// ---------------------------------------------------------------------------
// Kernel 1: main
// ---------------------------------------------------------------------------
__global__ void __launch_bounds__(NT, 2)
attn_main_kernel(const float* __restrict__ gout, const float* __restrict__ gv) {
    extern __shared__ char smem[];
    const uint32_t sb = smem_u32(smem);
    const int tid = threadIdx.x;
    const int wid = tid >> 5;
    const int lane = tid & 31;
    const int wm = wid & 1;          // M warp row: rows wm*32..+31
    const int wn = wid >> 1;         // N warp col: chunk cols wn*32..+31
    const int tile = blockIdx.x;
    const int bi = tile >> 6;
    const int ti = tile & 63;

    const float4* src4 =
        (const float4*)(gout + (size_t)(bi * S_DIM + ti * ROWS) * H_DIM);

    // ---- prefill W slices 0,1 (16KB each: 256 thr x 64B) ----
#pragma unroll
    for (int p = 0; p < 2; p++) {
        uint32_t dst = sb + SM_RING + p * SLICE_B + tid * 64;
        const unsigned char* s = g_W16 + p * SLICE_B + tid * 64;
        cp_async16(dst,      s);
        cp_async16(dst + 16, s + 16);
        cp_async16(dst + 32, s + 32);
        cp_async16(dst + 48, s + 48);
        CP_COMMIT();
    }

    // ---- A band loader: band s = K cols s*64..+63; 4 float4/thread ----
#define LOAD_BAND(S) do {                                                      \
        const int _s = (S);                                                    \
        _Pragma("unroll")                                                      \
        for (int i = 0; i < 4; i++) {                                          \
            int j = tid + i * NT;                                              \
            int r = j >> 4, c4 = j & 15;                                       \
            float4 f = src4[r * 128 + _s * 16 + c4];                           \
            __half2 h01 = __floats2half2_rn(f.x, f.y);                         \
            __half2 h23 = __floats2half2_rn(f.z, f.w);                         \
            uint2 val;                                                         \
            val.x = *reinterpret_cast<uint32_t*>(&h01);                        \
            val.y = *reinterpret_cast<uint32_t*>(&h23);                        \
            uint32_t off = (uint32_t)r * 1024u +                               \
                SWZ((uint32_t)(_s * 128 + c4 * 8), r);                         \
            *(uint2*)(smem + SM_A + off) = val;                                \
        }                                                                      \
    } while (0)

    LOAD_BAND(0);
    LOAD_BAND(1);

    // ---- ldmatrix lane addressing ----
    const int a_ln = (lane & 7) + ((lane >> 3) & 1) * 8;
    const uint32_t a_sw  = (a_ln & 7) << 4;
    const uint32_t a_t16 = (lane >> 4) * 16;
    const uint32_t a_base0 = sb + SM_A + (wm * 32 + a_ln) * 1024;

    const int b_ln = (lane & 7) + ((lane >> 4) & 1) * 8;
    const uint32_t b_sw  = (b_ln & 7) << 4;
    const uint32_t b_t16 = ((lane >> 3) & 1) * 16;
    const uint32_t b_roff = (uint32_t)(wn * 32 + b_ln) * 128u;

    float ca[2][4][4];
#pragma unroll
    for (int mi = 0; mi < 2; mi++)
#pragma unroll
        for (int j = 0; j < 4; j++)
#pragma unroll
            for (int q = 0; q < 4; q++) ca[mi][j][q] = 0.f;
    float sc[2][2] = {{0.f, 0.f}, {0.f, 0.f}};

    const float* gbias = g_bias + bi * H_DIM;

    // ---- mainloop over 32 W slices (chunk c = g>>3, K-slice s = g&7) ------
#pragma unroll 1
    for (int g = 0; g < NSLICE; g++) {
        CP_WAIT1();                     // slice g resident in slot g%3
        __syncthreads();                // + all warps done with slice g-1

        if (g + 2 < NSLICE) {           // slot (g+2)%3 == (g-1)%3: free now
            uint32_t dst = sb + SM_RING + ((g + 2) % RINGN) * SLICE_B + tid * 64;
            const unsigned char* s = g_W16 + (size_t)(g + 2) * SLICE_B + tid * 64;
            cp_async16(dst,      s);
            cp_async16(dst + 16, s + 16);
            cp_async16(dst + 32, s + 32);
            cp_async16(dst + 48, s + 48);
        }
        CP_COMMIT();                    // one group per iteration (may be empty)

        if (g < 6) LOAD_BAND(g + 2);    // A band g+2, first read at slice g+2

        const uint32_t wb = sb + SM_RING + (g % RINGN) * SLICE_B + b_roff;
        const uint32_t kbase = (uint32_t)(g & 7) * 128u;

#pragma unroll
        for (int ks = 0; ks < 4; ks++) {
            const uint32_t k2w = (uint32_t)ks * 32u;
            uint32_t a0[4], a1[4], b0[4], b1[4];
            const uint32_t akk = ((kbase + k2w) | a_t16) ^ a_sw;
            LDSM_X4(a0[0], a0[1], a0[2], a0[3], a_base0 + akk);
            LDSM_X4(a1[0], a1[1], a1[2], a1[3], a_base0 + 16 * 1024 + akk);
            const uint32_t bkk = (k2w | b_t16) ^ b_sw;
            LDSM_X4(b0[0], b0[1], b0[2], b0[3], wb + bkk);
            LDSM_X4(b1[0], b1[1], b1[2], b1[3], wb + 16 * 128 + bkk);

#define DOMMA(MI, AR)                                                          \
            MMA16816(ca[MI][0][0], ca[MI][0][1], ca[MI][0][2], ca[MI][0][3],   \
                     AR[0], AR[1], AR[2], AR[3], b0[0], b0[1]);                \
            MMA16816(ca[MI][1][0], ca[MI][1][1], ca[MI][1][2], ca[MI][1][3],   \
                     AR[0], AR[1], AR[2], AR[3], b0[2], b0[3]);                \
            MMA16816(ca[MI][2][0], ca[MI][2][1], ca[MI][2][2], ca[MI][2][3],   \
                     AR[0], AR[1], AR[2], AR[3], b1[0], b1[1]);                \
            MMA16816(ca[MI][3][0], ca[MI][3][1], ca[MI][3][2], ca[MI][3][3],   \
                     AR[0], AR[1], AR[2], AR[3], b1[2], b1[3]);
            DOMMA(0, a0)
            DOMMA(1, a1)
#undef DOMMA
        }

        // ---- per-chunk epilogue: tanh + dot v (bias/v from L2) ----
        if ((g & 7) == 7) {
            const int cb = (g >> 3) * 128 + wn * 32 + (lane & 3) * 2;
#pragma unroll
            for (int j = 0; j < 4; j++) {
                float2 bb = *(const float2*)(gbias + cb + j * 8);
                float2 vv = *(const float2*)(gv + cb + j * 8);
#pragma unroll
                for (int mi = 0; mi < 2; mi++) {
                    sc[mi][0] += tanh_fast(ca[mi][j][0] + bb.x) * vv.x
                               + tanh_fast(ca[mi][j][1] + bb.y) * vv.y;
                    sc[mi][1] += tanh_fast(ca[mi][j][2] + bb.x) * vv.x
                               + tanh_fast(ca[mi][j][3] + bb.y) * vv.y;
                    ca[mi][j][0] = 0.f; ca[mi][j][1] = 0.f;
                    ca[mi][j][2] = 0.f; ca[mi][j][3] = 0.f;
                }
            }
        }
    }

    // ---- ring region becomes scratch ----
    __syncthreads();
    float* sc2 = (float*)(smem + SM_SC2);      // [4][64] per N-warp-col
#pragma unroll
    for (int mi = 0; mi < 2; mi++)
#pragma unroll
        for (int h = 0; h < 2; h++) {
            float v = sc[mi][h];
            v += __shfl_xor_sync(0xffffffffu, v, 1);
            v += __shfl_xor_sync(0xffffffffu, v, 2);
            if ((lane & 3) == 0)
                sc2[wn * 64 + wm * 32 + mi * 16 + h * 8 + (lane >> 2)] = v;
        }
    __syncthreads();

    // ---- tile-local softmax over 64 rows ----
    float* sred = (float*)(smem + SM_RED);
    float scv = -1e30f;
    if (tid < 64) {
        scv = sc2[tid] + sc2[64 + tid] + sc2[128 + tid] + sc2[192 + tid];
        g_scores[bi * S_DIM + ti * ROWS + tid] = scv;
    }
    float m = scv;
#pragma unroll
    for (int o = 16; o; o >>= 1) m = fmaxf(m, __shfl_xor_sync(0xffffffffu, m, o));
    if (lane == 0 && wid < 2) sred[wid] = m;
    __syncthreads();
    float mt = fmaxf(sred[0], sred[1]);

    float w = (tid < 64) ? __expf(scv - mt) : 0.f;
    float ls = w;
#pragma unroll
    for (int o = 16; o; o >>= 1) ls += __shfl_xor_sync(0xffffffffu, ls, o);
    if (lane == 0 && wid < 2) sred[4 + wid] = ls;
    if (tid < 64) ((float*)(smem + SM_SW2))[tid] = w;
    __syncthreads();
    float lt = sred[4] + sred[5];
    if (tid == 0) { g_pm[tile] = mt; g_pl[tile] = lt; }

    // ---- partial context from SMEM fp16 A: one col pair per thread ----
    {
        const float* sw = (const float*)(smem + SM_SW2);
        const int col0 = tid * 2;
        float ax = 0.f, ay = 0.f;
#pragma unroll 4
        for (int s = 0; s < ROWS; s++) {
            float ws = sw[s];
            uint32_t off = (uint32_t)s * 1024u + SWZ((uint32_t)(col0 * 2), s);
            __half2 hv = *(const __half2*)(smem + SM_A + off);
            float2 f = __half22float2(hv);
            ax += ws * f.x;
            ay += ws * f.y;
        }
        g_pc[(size_t)tile * H_DIM + col0]     = ax;
        g_pc[(size_t)tile * H_DIM + col0 + 1] = ay;
    }
}

// ---------------------------------------------------------------------------
// Kernel 2: finalize — merge 64 tile partials per batch.
// ---------------------------------------------------------------------------
__global__ void finalize_kernel(float* __restrict__ dout) {
    const int bi = blockIdx.x;
    const int tid = threadIdx.x;

    float M = -1e30f;
#pragma unroll
    for (int t = 0; t < 64; t++) M = fmaxf(M, g_pm[bi * 64 + t]);
    float L = 0.f;
#pragma unroll
    for (int t = 0; t < 64; t++)
        L += g_pl[bi * 64 + t] * __expf(g_pm[bi * 64 + t] - M);
    const float invL = 1.0f / L;

    for (int h = tid; h < H_DIM; h += 256) {
        float acc = 0.f;
#pragma unroll
        for (int t = 0; t < 64; t++)
            acc += __expf(g_pm[bi * 64 + t] - M) *
                   g_pc[(size_t)(bi * 64 + t) * H_DIM + h];
        dout[bi * H_DIM + h] = acc * invL;
    }
    for (int s = tid; s < S_DIM; s += 256)
        dout[B_DIM * H_DIM + bi * S_DIM + s] =
            __expf(g_scores[bi * S_DIM + s] - M) * invL;
}

// ---------------------------------------------------------------------------
extern "C" void kernel_launch(void* const* d_in, const int* in_sizes, int n_in,
                              void* d_out, int out_size) {
    const float* out_t  = (const float*)d_in[0];
    const float* hidden = (const float*)d_in[1];
    const float* W      = (const float*)d_in[2];
    const float* bvec   = (const float*)d_in[3];
    const float* v      = (const float*)d_in[4];
    int hid_off = in_sizes[1] - B_DIM * H_DIM;

    cudaFuncSetAttribute(attn_main_kernel,
                         cudaFuncAttributeMaxDynamicSharedMemorySize, SM_TOTAL);

    prep_kernel<<<256, 256>>>(W, bvec, hidden, hid_off);
    pad_kernel<<<1, 32>>>();
    pad_kernel<<<1, 32>>>();
    attn_main_kernel<<<NTILES, NT, SM_TOTAL>>>(out_t, v);
    finalize_kernel<<<B_DIM, 256>>>((float*)d_out);
}

// round 8
// speedup vs baseline: 1.0631x; 1.0631x over previous
#include <cuda_runtime.h>
#include <cuda_fp16.h>
#include <cstdint>

// ---------------------------------------------------------------------------
// out (32,4096,512) f32, hidden (2,32,512), W (512,512), b(512), v(512)
// Output = [context (32*512) | attn (32*4096)] f32.
//
// R8: R7 with the B-address bug fixed (kbase is A-row-relative only; B slice
// rows are 128B wide, K-chunk already selected by the slice index).
// 1 CTA/SM, 512 thr, 4Mx4N warps (warp tile M32xN32), ROWS=128.
// W ring 6x16KB slots consumed/prefetched in PAIRS -> 16 barriers.
// B-fragment register double-buffer across ks. bias/v read from L2.
// ---------------------------------------------------------------------------
#define B_DIM   32
#define S_DIM   4096
#define H_DIM   512
#define ROWS    128
#define NTILES  1024
#define NSLICE  32
#define SLICE_B 16384
#define NT      512

// SMEM layout (bytes)
#define SM_A     0                  // 128 x 1024B fp16 rows (swizzled)
#define SM_RING  131072             // 6 x 16384
#define SM_SC2   131072             // scratch reusing ring after mainloop
#define SM_SW2   133120             // 128 f32 softmax weights
#define SM_RED   133632             // 16 f32
#define SM_CP    133760             // 512 f32 context-partial merge
#define SM_TOTAL 229376

#define SWZ(byte_in_row, row) ((byte_in_row) ^ (((row) & 7) << 4))

// -------------------- device-global scratch --------------------------------
__device__ __align__(16) unsigned char g_W16[H_DIM * H_DIM * 2];
__device__ float g_bias[B_DIM * H_DIM];
__device__ float g_scores[B_DIM * S_DIM];
__device__ float g_pm[NTILES];
__device__ float g_pl[NTILES];
__device__ float g_pc[NTILES * H_DIM];

// -------------------- helpers ----------------------------------------------
__device__ __forceinline__ uint32_t smem_u32(const void* p) {
    uint32_t a;
    asm("{ .reg .u64 t; cvta.to.shared.u64 t, %1; cvt.u32.u64 %0, t; }"
        : "=r"(a) : "l"(p));
    return a;
}
__device__ __forceinline__ void cp_async16(uint32_t dst, const void* src) {
    asm volatile("cp.async.cg.shared.global [%0], [%1], 16;"
                 :: "r"(dst), "l"(__cvta_generic_to_global(src)) : "memory");
}
#define CP_COMMIT() asm volatile("cp.async.commit_group;" ::: "memory")
#define CP_WAIT1()  asm volatile("cp.async.wait_group 1;" ::: "memory")

#define LDSM_X4(r0, r1, r2, r3, addr)                                          \
    asm volatile("ldmatrix.sync.aligned.m8n8.x4.shared.b16 {%0,%1,%2,%3}, [%4];" \
                 : "=r"(r0), "=r"(r1), "=r"(r2), "=r"(r3) : "r"(addr))

#define MMA16816(c0, c1, c2, c3, a0, a1, a2, a3, b0, b1)                       \
    asm volatile("mma.sync.aligned.m16n8k16.row.col.f32.f16.f16.f32 "          \
                 "{%0,%1,%2,%3}, {%4,%5,%6,%7}, {%8,%9}, {%0,%1,%2,%3};"       \
                 : "+f"(c0), "+f"(c1), "+f"(c2), "+f"(c3)                      \
                 : "r"(a0), "r"(a1), "r"(a2), "r"(a3), "r"(b0), "r"(b1))

__device__ __forceinline__ float tanh_fast(float x) {
    float e = __expf(2.0f * x);
    return 1.0f - __fdividef(2.0f, e + 1.0f);
}

// ---------------------------------------------------------------------------
// Kernel 0: prep — W f32 -> fp16 slice-major (slice g = (n>>7)*8 + (k>>6):
// 128 N-rows x 64 K-cols, 128B rows, SW128); bias = b + hidden[-1].
// ---------------------------------------------------------------------------
__global__ void prep_kernel(const float* __restrict__ W,
                            const float* __restrict__ bvec,
                            const float* __restrict__ hidden,
                            int hid_off) {
    int idx = blockIdx.x * blockDim.x + threadIdx.x;
    int stride = gridDim.x * blockDim.x;
    for (int i = idx; i < H_DIM * H_DIM; i += stride) {
        int n = i >> 9, k = i & 511;
        int g = (n >> 7) * 8 + (k >> 6);
        uint32_t off = (uint32_t)g * SLICE_B + (uint32_t)(n & 127) * 128u
                     + ((uint32_t)((k & 63) * 2) ^ (((uint32_t)n & 7) << 4));
        *(__half*)(g_W16 + off) = __float2half_rn(W[i]);
    }
    for (int i = idx; i < B_DIM * H_DIM; i += stride)
        g_bias[i] = bvec[i & 511] + hidden[hid_off + i];
}

__global__ void pad_kernel() {}

// ---------------------------------------------------------------------------
// Kernel 1: main
// ---------------------------------------------------------------------------
__global__ void __launch_bounds__(NT, 1)
attn_main_kernel(const float* __restrict__ gout, const float* __restrict__ gv) {
    extern __shared__ char smem[];
    const uint32_t sb = smem_u32(smem);
    const int tid = threadIdx.x;
    const int wid = tid >> 5;
    const int lane = tid & 31;
    const int wm = wid & 3;          // M warp row: rows wm*32..+31
    const int wn = wid >> 2;         // N warp col: chunk cols wn*32..+31
    const int tile = blockIdx.x;
    const int bi = tile >> 5;
    const int ti = tile & 31;

    const float4* src4 =
        (const float4*)(gout + (size_t)(bi * S_DIM + ti * ROWS) * H_DIM);

    // ---- prologue: W slice pairs (0,1) and (2,3); 32B/thread per slice ----
#pragma unroll
    for (int p = 0; p < 2; p++) {
#pragma unroll
        for (int q = 0; q < 2; q++) {
            int slice = p * 2 + q;
            uint32_t dst = sb + SM_RING + slice * SLICE_B + tid * 32;
            const unsigned char* s = g_W16 + (size_t)slice * SLICE_B + tid * 32;
            cp_async16(dst, s);
            cp_async16(dst + 16, s + 16);
        }
        CP_COMMIT();
    }

    // ---- A band loader: band s = K cols s*64..+63; 4 float4/thread ----
#define LOAD_BAND(S) do {                                                      \
        const int _s = (S);                                                    \
        _Pragma("unroll")                                                      \
        for (int i = 0; i < 4; i++) {                                          \
            int j = tid + i * NT;                                              \
            int r = j >> 4, c4 = j & 15;                                       \
            float4 f = src4[r * 128 + _s * 16 + c4];                           \
            __half2 h01 = __floats2half2_rn(f.x, f.y);                         \
            __half2 h23 = __floats2half2_rn(f.z, f.w);                         \
            uint2 val;                                                         \
            val.x = *reinterpret_cast<uint32_t*>(&h01);                        \
            val.y = *reinterpret_cast<uint32_t*>(&h23);                        \
            uint32_t off = (uint32_t)r * 1024u +                               \
                SWZ((uint32_t)(_s * 128 + c4 * 8), r);                         \
            *(uint2*)(smem + SM_A + off) = val;                                \
        }                                                                      \
    } while (0)

    LOAD_BAND(0);
    LOAD_BAND(1);

    // ---- ldmatrix lane addressing ----
    const int a_ln = (lane & 7) + ((lane >> 3) & 1) * 8;
    const uint32_t a_sw  = (a_ln & 7) << 4;
    const uint32_t a_t16 = (lane >> 4) * 16;
    const uint32_t a_base0 = sb + SM_A + (wm * 32 + a_ln) * 1024;

    const int b_ln = (lane & 7) + ((lane >> 4) & 1) * 8;
    const uint32_t b_sw  = (b_ln & 7) << 4;
    const uint32_t b_t16 = ((lane >> 3) & 1) * 16;
    const uint32_t b_roff = (uint32_t)(wn * 32 + b_ln) * 128u;

    float ca[2][4][4];
#pragma unroll
    for (int mi = 0; mi < 2; mi++)
#pragma unroll
        for (int j = 0; j < 4; j++)
#pragma unroll
            for (int q = 0; q < 4; q++) ca[mi][j][q] = 0.f;
    float sc[2][2] = {{0.f, 0.f}, {0.f, 0.f}};

    const float* gbias = g_bias + bi * H_DIM;

    // B fragments: slice rows are 128B wide; k2w is intra-row only [0,128).
#define LDSM_B(BUF, K2W) do {                                                  \
        const uint32_t _bkk = ((K2W) | b_t16) ^ b_sw;                          \
        LDSM_X4(rb[BUF][0][0], rb[BUF][0][1], rb[BUF][0][2], rb[BUF][0][3],    \
                wb + _bkk);                                                    \
        LDSM_X4(rb[BUF][1][0], rb[BUF][1][1], rb[BUF][1][2], rb[BUF][1][3],    \
                wb + 16 * 128 + _bkk);                                         \
    } while (0)

    // ---- mainloop: 16 rounds x 2 slices (slice g: chunk c=g>>3, band s=g&7)
#pragma unroll 1
    for (int r = 0; r < 16; r++) {
        CP_WAIT1();                     // pair r resident (pair r+1 in flight)
        __syncthreads();

        if (r + 2 < 16) {               // prefetch pair r+2 into pair r-1 slots
#pragma unroll
            for (int q = 0; q < 2; q++) {
                int slice = 2 * r + 4 + q;
                uint32_t dst = sb + SM_RING + (slice % 6) * SLICE_B + tid * 32;
                const unsigned char* s =
                    g_W16 + (size_t)slice * SLICE_B + tid * 32;
                cp_async16(dst, s);
                cp_async16(dst + 16, s + 16);
            }
        }
        CP_COMMIT();                    // one group per round (may be empty)

        if (r < 3) { LOAD_BAND(2 * r + 2); LOAD_BAND(2 * r + 3); }

#pragma unroll
        for (int sl = 0; sl < 2; sl++) {
            const int g = 2 * r + sl;
            const uint32_t wb = sb + SM_RING + (g % 6) * SLICE_B + b_roff;
            const uint32_t kbase = (uint32_t)(g & 7) * 128u;   // A rows only

            uint32_t rb[2][2][4];
            LDSM_B(0, 0u);

#pragma unroll
            for (int ks = 0; ks < 4; ks++) {
                const int cur = ks & 1;
                if (ks < 3) LDSM_B(cur ^ 1, (uint32_t)(ks + 1) * 32u);

                uint32_t a0[4], a1[4];
                const uint32_t akk =
                    ((kbase + (uint32_t)ks * 32u) | a_t16) ^ a_sw;
                LDSM_X4(a0[0], a0[1], a0[2], a0[3], a_base0 + akk);
                LDSM_X4(a1[0], a1[1], a1[2], a1[3], a_base0 + 16 * 1024 + akk);

#define DOMMA(MI, AR)                                                          \
                MMA16816(ca[MI][0][0], ca[MI][0][1], ca[MI][0][2],             \
                         ca[MI][0][3], AR[0], AR[1], AR[2], AR[3],             \
                         rb[cur][0][0], rb[cur][0][1]);                        \
                MMA16816(ca[MI][1][0], ca[MI][1][1], ca[MI][1][2],             \
                         ca[MI][1][3], AR[0], AR[1], AR[2], AR[3],             \
                         rb[cur][0][2], rb[cur][0][3]);                        \
                MMA16816(ca[MI][2][0], ca[MI][2][1], ca[MI][2][2],             \
                         ca[MI][2][3], AR[0], AR[1], AR[2], AR[3],             \
                         rb[cur][1][0], rb[cur][1][1]);                        \
                MMA16816(ca[MI][3][0], ca[MI][3][1], ca[MI][3][2],             \
                         ca[MI][3][3], AR[0], AR[1], AR[2], AR[3],             \
                         rb[cur][1][2], rb[cur][1][3]);
                DOMMA(0, a0)
                DOMMA(1, a1)
#undef DOMMA
            }

            // ---- per-chunk epilogue: tanh + dot v (bias/v from L2) ----
            if ((g & 7) == 7) {
                const int cb = (g >> 3) * 128 + wn * 32 + (lane & 3) * 2;
#pragma unroll
                for (int j = 0; j < 4; j++) {
                    float2 bb = *(const float2*)(gbias + cb + j * 8);
                    float2 vv = *(const float2*)(gv + cb + j * 8);
#pragma unroll
                    for (int mi = 0; mi < 2; mi++) {
                        sc[mi][0] += tanh_fast(ca[mi][j][0] + bb.x) * vv.x
                                   + tanh_fast(ca[mi][j][1] + bb.y) * vv.y;
                        sc[mi][1] += tanh_fast(ca[mi][j][2] + bb.x) * vv.x
                                   + tanh_fast(ca[mi][j][3] + bb.y) * vv.y;
                        ca[mi][j][0] = 0.f; ca[mi][j][1] = 0.f;
                        ca[mi][j][2] = 0.f; ca[mi][j][3] = 0.f;
                    }
                }
            }
        }
    }

    // ---- ring region becomes scratch ----
    __syncthreads();
    float* sc2 = (float*)(smem + SM_SC2);      // [4][128] per N-warp-col
#pragma unroll
    for (int mi = 0; mi < 2; mi++)
#pragma unroll
        for (int h = 0; h < 2; h++) {
            float v = sc[mi][h];
            v += __shfl_xor_sync(0xffffffffu, v, 1);
            v += __shfl_xor_sync(0xffffffffu, v, 2);
            if ((lane & 3) == 0)
                sc2[wn * 128 + wm * 32 + mi * 16 + h * 8 + (lane >> 2)] = v;
        }
    __syncthreads();

    // ---- tile-local softmax over 128 rows ----
    float* sred = (float*)(smem + SM_RED);
    float scv = -1e30f;
    if (tid < 128) {
        scv = sc2[tid] + sc2[128 + tid] + sc2[256 + tid] + sc2[384 + tid];
        g_scores[bi * S_DIM + ti * ROWS + tid] = scv;
    }
    float m = scv;
#pragma unroll
    for (int o = 16; o; o >>= 1) m = fmaxf(m, __shfl_xor_sync(0xffffffffu, m, o));
    if (lane == 0 && wid < 4) sred[wid] = m;
    __syncthreads();
    float mt = fmaxf(fmaxf(sred[0], sred[1]), fmaxf(sred[2], sred[3]));

    float w = (tid < 128) ? __expf(scv - mt) : 0.f;
    float ls = w;
#pragma unroll
    for (int o = 16; o; o >>= 1) ls += __shfl_xor_sync(0xffffffffu, ls, o);
    if (lane == 0 && wid < 4) sred[8 + wid] = ls;
    if (tid < 128) ((float*)(smem + SM_SW2))[tid] = w;
    __syncthreads();
    float lt = sred[8] + sred[9] + sred[10] + sred[11];
    if (tid == 0) { g_pm[tile] = mt; g_pl[tile] = lt; }

    // ---- partial context: 256 col-pairs x 2 row-halves ----
    {
        const float* sw = (const float*)(smem + SM_SW2);
        float* cpart = (float*)(smem + SM_CP);
        const int col0 = (tid & 255) * 2;
        const int r0 = (tid >> 8) * 64;
        float ax = 0.f, ay = 0.f;
#pragma unroll 4
        for (int s = 0; s < 64; s++) {
            int row = r0 + s;
            float ws = sw[row];
            uint32_t off = (uint32_t)row * 1024u + SWZ((uint32_t)(col0 * 2), row);
            __half2 hv = *(const __half2*)(smem + SM_A + off);
            float2 f = __half22float2(hv);
            ax += ws * f.x;
            ay += ws * f.y;
        }
        if (tid >= 256) {
            cpart[(tid - 256) * 2]     = ax;
            cpart[(tid - 256) * 2 + 1] = ay;
        }
        __syncthreads();
        if (tid < 256) {
            ax += cpart[tid * 2];
            ay += cpart[tid * 2 + 1];
            g_pc[(size_t)tile * H_DIM + col0]     = ax;
            g_pc[(size_t)tile * H_DIM + col0 + 1] = ay;
        }
    }
}

// ---------------------------------------------------------------------------
// Kernel 2: finalize — merge 32 tile partials per batch.
// ---------------------------------------------------------------------------
__global__ void finalize_kernel(float* __restrict__ dout) {
    const int bi = blockIdx.x;
    const int tid = threadIdx.x;

    float M = -1e30f;
#pragma unroll
    for (int t = 0; t < 32; t++) M = fmaxf(M, g_pm[bi * 32 + t]);
    float L = 0.f;
#pragma unroll
    for (int t = 0; t < 32; t++)
        L += g_pl[bi * 32 + t] * __expf(g_pm[bi * 32 + t] - M);
    const float invL = 1.0f / L;

    for (int h = tid; h < H_DIM; h += 256) {
        float acc = 0.f;
#pragma unroll
        for (int t = 0; t < 32; t++)
            acc += __expf(g_pm[bi * 32 + t] - M) *
                   g_pc[(size_t)(bi * 32 + t) * H_DIM + h];
        dout[bi * H_DIM + h] = acc * invL;
    }
    for (int s = tid; s < S_DIM; s += 256)
        dout[B_DIM * H_DIM + bi * S_DIM + s] =
            __expf(g_scores[bi * S_DIM + s] - M) * invL;
}

// ---------------------------------------------------------------------------
extern "C" void kernel_launch(void* const* d_in, const int* in_sizes, int n_in,
                              void* d_out, int out_size) {
    const float* out_t  = (const float*)d_in[0];
    const float* hidden = (const float*)d_in[1];
    const float* W      = (const float*)d_in[2];
    const float* bvec   = (const float*)d_in[3];
    const float* v      = (const float*)d_in[4];
    int hid_off = in_sizes[1] - B_DIM * H_DIM;

    cudaFuncSetAttribute(attn_main_kernel,
                         cudaFuncAttributeMaxDynamicSharedMemorySize, SM_TOTAL);

    prep_kernel<<<256, 256>>>(W, bvec, hidden, hid_off);
    pad_kernel<<<1, 32>>>();
    pad_kernel<<<1, 32>>>();
    attn_main_kernel<<<NTILES, NT, SM_TOTAL>>>(out_t, v);
    finalize_kernel<<<B_DIM, 256>>>((float*)d_out);
}